// round 8
// baseline (speedup 1.0000x reference)
#include <cuda_runtime.h>
#include <cstddef>
#include <cstdint>

// CTC loss forward, fused single-kernel. B=32, T=800, C=5000, L=100, S=201.
//
// R7 vs R6 (127.7us, alpha ~300cyc/step):
//  * Root cause of the 300cyc step: the per-step scattered-LDG refill burst
//    (~130 L1tex wavefronts/SM) was issued BEFORE the critical exchange LDS,
//    which therefore queued behind the whole burst. Fix: asm-volatile pinned
//    order  LDS -> compute -> STS -> LDG refills -> bar.  The FIFO drains
//    during compute+barrier, so the next step's LDS sees an empty queue.
//  * Exchange is float2 (neighbor's odd pair only) instead of float4.
//  * Blank (2-term) update uses a single ex2 via the ex2(-|d|) select trick.
//  * No divergence in the loop: threads 101..127 compute dummy states into
//    padded smem slots.
//  * reduce: deterministic warp tree instead of 32 serial L2-latency loads.

#define Bb 32
#define Tt 800
#define Cc 5000
#define Ll 100
#define NT 101            // thread i owns states 2i, 2i+1
#define NEGV (-1e30f)
#define LOG2E 1.4426950408889634f
#define LN2   0.6931471805599453f
#define DPF 8             // emission prefetch depth
#define RENORM 32
#define SLOTS 130         // 1 dead pad + 128 threads + 1 spare

__device__ float g_tot[Bb];

__device__ __forceinline__ float ex2f(float x) {
    float y; asm("ex2.approx.ftz.f32 %0, %1;" : "=f"(y) : "f"(x)); return y;
}
__device__ __forceinline__ float lg2f(float x) {
    float y; asm("lg2.approx.ftz.f32 %0, %1;" : "=f"(y) : "f"(x)); return y;
}

// ---------------------------------------------------------------------------
// Fused gather + alpha recursion. grid = B blocks, 128 threads (4 warps).
// ---------------------------------------------------------------------------
__global__ __launch_bounds__(128, 1)
void ctc_alpha_fused(const float* __restrict__ lp,
                     const int* __restrict__ targets,
                     const int* __restrict__ ilen,
                     const int* __restrict__ tlen)
{
    // ex[buf][slot] = (base, sum) of a thread's ODD state. slot0 = dead pad.
    __shared__ float2 ex[2][SLOTS];
    __shared__ float4 fin[SLOTS];        // final (be,se,bo,so) per thread

    const int b = blockIdx.x;
    const int i = threadIdx.x;
    const int last = ilen[b] - 1;        // >= 600 here

    const int  tg   = (i < Ll) ? targets[b * Ll + i] : 0;
    const int  tgp  = (i >= 1 && i <= Ll) ? targets[b * Ll + i - 1] : -1;
    const bool skip = (tg != tgp);

    const float* __restrict__ rowb = lp + (size_t)b * Tt * Cc;

    const uint32_t sbase  = (uint32_t)__cvta_generic_to_shared(&ex[0][0]);
    const uint32_t STRIDE = SLOTS * 8;   // bytes per buffer

    if (i == 0) {
        ex[0][0] = make_float2(NEGV, 0.f);
        ex[1][0] = make_float2(NEGV, 0.f);
    }

    // t=0 init (log2 domain, alpha = base + lg2(sum)): states 0,1 live.
    float se = 1.f, so = 1.f;
    float be = (i == 0) ? LOG2E * rowb[0]  : NEGV;
    float bo = (i == 0) ? LOG2E * rowb[tg] : NEGV;
    ex[0][i + 1] = make_float2(bo, so);

    // Depth-8 emission prefetch rings (blank col 0 broadcast + own target col).
    float eb[DPF], eo[DPF];
#pragma unroll
    for (int k = 0; k < DPF; ++k) {
        int tt = 1 + k; if (tt > last) tt = last;
        const float* p = rowb + (size_t)tt * Cc;
        eb[k] = p[0];
        eo[k] = p[tg];
    }
    __syncthreads();

    uint32_t off = 0;
#pragma unroll 8
    for (int t = 1; t <= last; ++t) {
        const int k = (t - 1) & (DPF - 1);

        // (1) critical exchange LDS first -- empty FIFO at this point.
        float nbz, nbw;                  // neighbor's odd (base, sum)
        asm volatile("ld.shared.v2.f32 {%0, %1}, [%2];"
                     : "=f"(nbz), "=f"(nbw)
                     : "r"(sbase + off + i * 8));

        const float ecb = LOG2E * eb[k];
        const float eco = LOG2E * eo[k];

        // (2) compute.
        // even state 2i (blank, 2 preds): single-ex2 logaddexp.
        float d  = be - nbz;
        float tm = ex2f(fminf(d, -d));           // ex2(-|d|)
        float me = fmaxf(be, nbz);
        float te = (d >= 0.f) ? fmaf(nbw, tm, se) : fmaf(se, tm, nbw);
        // odd state 2i+1 (3 preds): parallel 3x ex2.
        float b3 = skip ? nbz : NEGV;
        float s3 = skip ? nbw : 0.f;
        float mo = fmaxf(fmaxf(bo, be), b3);
        float to = so * ex2f(bo - mo) + se * ex2f(be - mo)
                 + s3 * ex2f(b3 - mo);
        be = me + ecb; se = te;
        bo = mo + eco; so = to;
        if ((t & (RENORM - 1)) == 0) {           // fold, off 31/32 steps
            be = fmaxf(be + lg2f(se), NEGV); se = 1.f;
            bo = fmaxf(bo + lg2f(so), NEGV); so = 1.f;
        }

        // (3) STS of odd pair -- ahead of the LDG burst so the barrier's STS
        //     drain isn't stuck behind it.
        asm volatile("st.shared.v2.f32 [%0], {%1, %2};"
                     :: "r"(sbase + (off ^ STRIDE) + (i + 1) * 8),
                        "f"(bo), "f"(so) : "memory");

        // (4) prefetch refills LAST (t+DPF); they drain during compute+bar.
        int tp = t + DPF; if (tp > last) tp = last;
        const float* p = rowb + (size_t)tp * Cc;
        asm volatile("ld.global.nc.f32 %0, [%1];" : "=f"(eb[k]) : "l"(p) : "memory");
        asm volatile("ld.global.nc.f32 %0, [%1];" : "=f"(eo[k]) : "l"(p + tg) : "memory");

        __syncthreads();
        off ^= STRIDE;
    }

    // Publish final states, then thread 0 scores.
    fin[i + 1] = make_float4(be, se, bo, so);
    __syncthreads();
    if (i == 0) {
        int Lb = tlen[b];
        float4 ve = fin[Lb + 1];         // even of thread Lb   -> state 2Lb
        float4 vo = fin[Lb];             // odd  of thread Lb-1 -> state 2Lb-1
        float x = ve.x + lg2f(ve.y);
        float y = vo.z + lg2f(vo.w);
        float m = fmaxf(x, y);
        g_tot[b] = LN2 * (m + lg2f(ex2f(x - m) + ex2f(y - m)));
    }
}

// ---------------------------------------------------------------------------
// Deterministic parallel reduction (fixed warp tree).
// ---------------------------------------------------------------------------
__global__ void reduce_kernel(const int* __restrict__ ilen,
                              float* __restrict__ out) {
    int b = threadIdx.x;                 // 32 threads
    float tot = g_tot[b];
    float il  = (float)ilen[b];
    bool  fin = tot > NEGV * 0.5f;
    float ts = fin ? tot : 0.f;
    float tf = fin ? il  : 0.f;
    float af = il;
#pragma unroll
    for (int s = 16; s >= 1; s >>= 1) {
        ts += __shfl_down_sync(0xFFFFFFFFu, ts, s);
        tf += __shfl_down_sync(0xFFFFFFFFu, tf, s);
        af += __shfl_down_sync(0xFFFFFFFFu, af, s);
    }
    if (b == 0) { out[0] = ts; out[1] = tf; out[2] = af; }
}

// ---------------------------------------------------------------------------
extern "C" void kernel_launch(void* const* d_in, const int* in_sizes, int n_in,
                              void* d_out, int out_size) {
    const float* lp      = (const float*)d_in[0];  // nnet_output [B,T,C] f32
    const int*   targets = (const int*)  d_in[1];  // [B,L] i32
    const int*   ilen    = (const int*)  d_in[2];  // [B] i32
    const int*   tlen    = (const int*)  d_in[3];  // [B] i32

    ctc_alpha_fused<<<Bb, 128>>>(lp, targets, ilen, tlen);
    reduce_kernel<<<1, 32>>>(ilen, (float*)d_out);
}